// round 9
// baseline (speedup 1.0000x reference)
#include <cuda_runtime.h>
#include <cuda_bf16.h>
#include <math.h>

#define CDIM   128
#define LTOK   54
#define NTOK   8
#define LN_EPS 1e-5f
#define SAW    68      // smem row stride in bf16x2 words (17x16B -> ldmatrix conflict-free)
#define SDW    33      // dots row stride in bf16x2 words

// ---------------- device globals (precomputed weights) ----------------
__device__ uint2 g_WcB [8 * 24 * 32];   // combined [A_fold | Wv] bf16 B-frags
__device__ uint2 g_WpB [8 * 16 * 32];   // Wp  bf16 B-frags
__device__ uint2 g_Wf1B[8 * 16 * 32];   // Wf1 bf16 B-frags
__device__ uint2 g_Wf2B[8 * 16 * 32];   // Wf2 bf16 B-frags

// ---------------- helpers ----------------
__device__ __forceinline__ unsigned bfpack(float lo, float hi) {
    __nv_bfloat162 h = __floats2bfloat162_rn(lo, hi);
    return *(unsigned*)&h;
}
__device__ __forceinline__ float2 bfunpack(unsigned u) {
    return __bfloat1622float2(*(__nv_bfloat162*)&u);
}

__device__ __forceinline__ void mma_bf16(float* c, const unsigned* a, unsigned b0, unsigned b1) {
    asm volatile(
        "mma.sync.aligned.m16n8k16.row.col.f32.bf16.bf16.f32 "
        "{%0,%1,%2,%3},{%4,%5,%6,%7},{%8,%9},{%0,%1,%2,%3};"
        : "+f"(c[0]), "+f"(c[1]), "+f"(c[2]), "+f"(c[3])
        : "r"(a[0]), "r"(a[1]), "r"(a[2]), "r"(a[3]), "r"(b0), "r"(b1));
}

__device__ __forceinline__ void ldsm_x4(unsigned* r, unsigned saddr) {
    asm volatile(
        "ldmatrix.sync.aligned.m8n8.x4.shared.b16 {%0,%1,%2,%3}, [%4];"
        : "=r"(r[0]), "=r"(r[1]), "=r"(r[2]), "=r"(r[3]) : "r"(saddr));
}

__device__ __forceinline__ float warp_sum(float v) {
    v += __shfl_xor_sync(0xffffffffu, v, 16);
    v += __shfl_xor_sync(0xffffffffu, v, 8);
    v += __shfl_xor_sync(0xffffffffu, v, 4);
    v += __shfl_xor_sync(0xffffffffu, v, 2);
    v += __shfl_xor_sync(0xffffffffu, v, 1);
    return v;
}

// ---------------- precompute: 72 blocks x 256 threads = 18432 pack items ----------------
__global__ __launch_bounds__(256, 4) void precompute_kernel(
    const float* __restrict__ query,
    const float* __restrict__ ln1_g, const float* __restrict__ ln1_b,
    const float* __restrict__ Wq, const float* __restrict__ bq,
    const float* __restrict__ Wk,
    const float* __restrict__ Wv,
    const float* __restrict__ Wp,
    const float* __restrict__ Wf1,
    const float* __restrict__ Wf2)
{
    __shared__ float s_qn[NTOK * CDIM];
    __shared__ float s_q[NTOK * CDIM];
    const int tid = threadIdx.x;
    const int warp = tid >> 5, lane = tid & 31;

    if (warp < NTOK) {
        const int r = warp;
        float4 xv = *(const float4*)&query[r * CDIM + lane * 4];
        float s1 = xv.x + xv.y + xv.z + xv.w;
        float s2 = xv.x * xv.x + xv.y * xv.y + xv.z * xv.z + xv.w * xv.w;
        s1 = warp_sum(s1);
        s2 = warp_sum(s2);
        float m = s1 * (1.0f / 128.0f);
        float var = s2 * (1.0f / 128.0f) - m * m;
        float rs = rsqrtf(var + LN_EPS);
        float4 g = *(const float4*)&ln1_g[lane * 4];
        float4 be = *(const float4*)&ln1_b[lane * 4];
        float4 o;
        o.x = (xv.x - m) * rs * g.x + be.x;
        o.y = (xv.y - m) * rs * g.y + be.y;
        o.z = (xv.z - m) * rs * g.z + be.z;
        o.w = (xv.w - m) * rs * g.w + be.w;
        *(float4*)&s_qn[r * CDIM + lane * 4] = o;
    }
    __syncthreads();

    #pragma unroll
    for (int j = 0; j < 4; j++) {
        const int idx = tid + j * 256;
        const int t = idx >> 7, o = idx & 127;
        float acc = bq[o];
        #pragma unroll 8
        for (int c = 0; c < CDIM; c++)
            acc += s_qn[t * CDIM + c] * __ldg(Wq + c * CDIM + o);
        s_q[idx] = acc;
    }
    __syncthreads();

    const int gid = blockIdx.x * 256 + tid;
    if (gid < 6144) {
        const int lane2 = gid & 31;
        const int rest = gid >> 5;
        const int nt = rest % 24;
        const int ks = rest / 24;
        const int g = lane2 >> 2, t = lane2 & 3;
        const int c = nt * 8 + g;
        const int k0 = ks * 16 + 2 * t;
        float f0, f1, f2, f3;
        if (c < 64) {
            // A_fold: bk folds to per-column constant -> cancels in softmax
            const int tok = c >> 3, h = c & 7;
            const float* qv = s_q + tok * CDIM + h * 16;
            float a0 = 0.f, a1 = 0.f, a2 = 0.f, a3 = 0.f;
            #pragma unroll
            for (int j = 0; j < 16; j++) {
                const float qj = qv[j];
                a0 += qj * __ldg(Wk + (k0    ) * CDIM + h * 16 + j);
                a1 += qj * __ldg(Wk + (k0 + 1) * CDIM + h * 16 + j);
                a2 += qj * __ldg(Wk + (k0 + 8) * CDIM + h * 16 + j);
                a3 += qj * __ldg(Wk + (k0 + 9) * CDIM + h * 16 + j);
            }
            f0 = 0.25f * a0; f1 = 0.25f * a1; f2 = 0.25f * a2; f3 = 0.25f * a3;
        } else {
            const int cc = c - 64;
            f0 = __ldg(Wv + (k0    ) * CDIM + cc);
            f1 = __ldg(Wv + (k0 + 1) * CDIM + cc);
            f2 = __ldg(Wv + (k0 + 8) * CDIM + cc);
            f3 = __ldg(Wv + (k0 + 9) * CDIM + cc);
        }
        g_WcB[gid] = make_uint2(bfpack(f0, f1), bfpack(f2, f3));
    } else {
        const int r = (gid - 6144) & 4095;
        const int m = (gid - 6144) >> 12;
        const int lane2 = r & 31;
        const int rest = r >> 5;
        const int nt = rest & 15;
        const int ks = rest >> 4;
        const int g = lane2 >> 2, t = lane2 & 3;
        const int c = nt * 8 + g;
        const int k0 = ks * 16 + 2 * t;
        const float* W = (m == 0) ? Wp : (m == 1) ? Wf1 : Wf2;
        uint2 v = make_uint2(
            bfpack(__ldg(W + k0 * CDIM + c), __ldg(W + (k0 + 1) * CDIM + c)),
            bfpack(__ldg(W + (k0 + 8) * CDIM + c), __ldg(W + (k0 + 9) * CDIM + c)));
        if (m == 0)      g_WpB [r] = v;
        else if (m == 1) g_Wf1B[r] = v;
        else             g_Wf2B[r] = v;
    }
}

// ---------------- persistent megakernel: 512 threads, 2 blocks/SM ----------------
// smem layout (4B words):
//   sA  [128][SAW] bf16x2 : tgt (2x64 rows) -> V overwrite     8704 w
//   sB  [6144]     uint2  : GEMM1 B-frags (staged ONCE)        12288 w
//   sDb [108][SDW] bf16x2 : dots (bf16); sF overlays here      3564 w
//   sAt [16][SAW]  bf16x2 : attn out / LN2 out                 1088 w
//   sX  [16][128]  fp32   : residual x                         2048 w
#define W_A   (128 * SAW)
#define W_B   (6144 * 2)
#define W_D   (108 * SDW)
#define W_AT  (16 * SAW)
#define W_X   (16 * 128)
#define OFF_B  (W_A)
#define OFF_D  (W_A + W_B)
#define OFF_AT (W_A + W_B + W_D)
#define OFF_X  (W_A + W_B + W_D + W_AT)
#define SM_MEGA_BYTES ((W_A + W_B + W_D + W_AT + W_X) * 4)

__global__ __launch_bounds__(512, 2) void mega_kernel(
    const float* __restrict__ tgt,
    const float* __restrict__ query,
    const float* __restrict__ bv,
    const float* __restrict__ bp,
    const float* __restrict__ ln2_g, const float* __restrict__ ln2_b,
    const float* __restrict__ bf1, const float* __restrict__ bf2,
    float* __restrict__ out, int npairs)
{
    extern __shared__ unsigned smw[];
    unsigned* sA  = smw;
    uint2*    sB  = (uint2*)(smw + OFF_B);
    unsigned* sDb = smw + OFF_D;
    unsigned* sF  = smw + OFF_D;          // overlays dots (dead when sF live)
    unsigned* sAt = smw + OFF_AT;
    float*    sX  = (float*)(smw + OFF_X);

    const int tid = threadIdx.x;
    const int w = tid >> 5, lane = tid & 31;
    const int g = lane >> 2, t = lane & 3;

    const unsigned sA_u32  = (unsigned)__cvta_generic_to_shared(sA);
    const unsigned sAt_u32 = (unsigned)__cvta_generic_to_shared(sAt);
    const unsigned sF_u32  = (unsigned)__cvta_generic_to_shared(sF);
    const unsigned laneoff = (((lane & 15) * SAW + (lane >> 4) * 4) << 2);

    // ---- stage GEMM1 B-fragments ONCE per block ----
    {
        const uint4* src = (const uint4*)g_WcB;
        uint4* dst = (uint4*)sB;
        #pragma unroll
        for (int i = 0; i < 6; i++)
            dst[tid + i * 512] = __ldg(src + tid + i * 512);
    }

    for (int pair = blockIdx.x; pair < npairs; pair += gridDim.x) {
        const int b0 = pair * 2;
        __syncthreads();   // protect sA / sDb(sF) reuse across iterations

        // ---- Phase 0: stage tgt (2 batches, 108 rows) as bf16 ----
        {
            const float4* gt = (const float4*)(tgt + (size_t)b0 * (LTOK * CDIM));
            #pragma unroll
            for (int i0 = 0; i0 < 7; i0++) {
                const int i = tid + i0 * 512;
                if (i < 2 * LTOK * 32) {
                    const int row = i >> 5, c4 = i & 31;
                    float4 v = __ldg(gt + i);
                    const int bb = (row >= LTOK) ? 1 : 0;
                    const int r = row - bb * LTOK;
                    *(uint2*)&sA[(bb * 64 + r) * SAW + c4 * 2] =
                        make_uint2(bfpack(v.x, v.y), bfpack(v.z, v.w));
                }
            }
        }
        __syncthreads();

        // ---- Phase 1: GEMM1 merged single pass: 2m x 6n per warp ----
        //      [128(2x54),128] @ [128,192] -> dots (nt<8) | V (nt 8..23)
        {
            const int a = w & 3;          // m-tile pair {2a, 2a+1}
            const int e = w >> 2;         // n-group: tiles e*6 .. e*6+5
            float C[2][6][4];
            #pragma unroll
            for (int m = 0; m < 2; m++)
                #pragma unroll
                for (int n = 0; n < 6; n++)
                    #pragma unroll
                    for (int q = 0; q < 4; q++) C[m][n][q] = 0.0f;

            const int bbase = e * 6;
            #pragma unroll 1
            for (int ks = 0; ks < 8; ks++) {
                unsigned A0[4], A1[4];
                ldsm_x4(A0, sA_u32 + (((a * 2    ) * 16 * SAW + ks * 8) << 2) + laneoff);
                ldsm_x4(A1, sA_u32 + (((a * 2 + 1) * 16 * SAW + ks * 8) << 2) + laneoff);
                const uint2* brow = &sB[(ks * 24 + bbase) * 32 + lane];
                #pragma unroll
                for (int n = 0; n < 6; n++) {
                    const uint2 B = brow[n * 32];
                    mma_bf16(C[0][n], A0, B.x, B.y);
                    mma_bf16(C[1][n], A1, B.x, B.y);
                }
            }
            __syncthreads();   // ALL A reads done before V overwrites sA

            #pragma unroll
            for (int m = 0; m < 2; m++) {
                const int r1 = (a * 2 + m) * 16 + g;   // global row 0..127
                const int bb = r1 >> 6, rl = r1 & 63;
                #pragma unroll
                for (int n = 0; n < 6; n++) {
                    const int nt = bbase + n;
                    if (nt < 8) {
                        const int wrd = nt * 4 + t;
                        unsigned* d0 = sDb + (bb * LTOK + rl) * SDW + wrd;
                        if (rl < LTOK)     d0[0]       = bfpack(C[m][n][0], C[m][n][1]);
                        if (rl + 8 < LTOK) d0[8 * SDW] = bfpack(C[m][n][2], C[m][n][3]);
                    } else {
                        const int wrd = (nt - 8) * 4 + t;
                        unsigned* v0 = sA + r1 * SAW + wrd;
                        if (rl < LTOK)     v0[0]       = bfpack(C[m][n][0], C[m][n][1]);
                        if (rl + 8 < LTOK) v0[8 * SAW] = bfpack(C[m][n][2], C[m][n][3]);
                    }
                }
            }
        }
        __syncthreads();

        // ---- Phase 2: softmax + AV: 512 tasks (2b x 8tok x 8head x 4quarter) ----
        {
            const int bb = tid >> 8;
            const int rest = tid & 255;
            const int th = rest >> 2, qt = rest & 3;
            const int tok = th >> 3, h = th & 7;
            const int ridx = (tok < 2) ? tok : (tok - 2);
            const int hb = ridx / 3, wb = ridx % 3;
            const int l0 = hb * 27 + wb * 3;
            int ls[9];
            #pragma unroll
            for (int d = 0; d < 9; d++) ls[d] = l0 + (d / 3) * 9 + (d % 3);

            const int dw = th >> 1, dh = th & 1;
            float dv[9];
            float mx = -1e30f;
            #pragma unroll
            for (int d = 0; d < 9; d++) {
                float2 p = bfunpack(sDb[(bb * LTOK + ls[d]) * SDW + dw]);
                dv[d] = dh ? p.y : p.x;
                mx = fmaxf(mx, dv[d]);
            }
            float ssum = 0.0f;
            #pragma unroll
            for (int d = 0; d < 9; d++) {
                dv[d] = __expf(dv[d] - mx);
                ssum += dv[d];
            }
            const float inv = 1.0f / ssum;
            float acc[4] = {0.f, 0.f, 0.f, 0.f};
            #pragma unroll
            for (int d = 0; d < 9; d++) {
                const uint2 vv = *(const uint2*)&sA[(bb * 64 + ls[d]) * SAW + h * 8 + qt * 2];
                float2 p;
                p = bfunpack(vv.x); acc[0] += dv[d] * p.x; acc[1] += dv[d] * p.y;
                p = bfunpack(vv.y); acc[2] += dv[d] * p.x; acc[3] += dv[d] * p.y;
            }
            const int cb = h * 16 + qt * 4;
            const float b0v = __ldg(bv + cb),     b1v = __ldg(bv + cb + 1);
            const float b2v = __ldg(bv + cb + 2), b3v = __ldg(bv + cb + 3);
            *(uint2*)&sAt[(bb * 8 + tok) * SAW + h * 8 + qt * 2] = make_uint2(
                bfpack(acc[0] * inv + b0v, acc[1] * inv + b1v),
                bfpack(acc[2] * inv + b2v, acc[3] * inv + b3v));
        }
        __syncthreads();

        // ===== tail: M=16 x 128 GEMMs, warp w owns n-tile w (full k) =====

        // ---- Phase 3: proj: x = query + attn @ Wp + bp -> sX ----
        {
            float C[4] = {0.f, 0.f, 0.f, 0.f};
            #pragma unroll
            for (int ks = 0; ks < 8; ks++) {
                unsigned A4[4];
                ldsm_x4(A4, sAt_u32 + ((ks * 8) << 2) + laneoff);
                uint2 bb2 = __ldg(&g_WpB[(ks * 16 + w) * 32 + lane]);
                mma_bf16(C, A4, bb2.x, bb2.y);
            }
            const int c0 = w * 8 + 2 * t;
            const float bp0 = __ldg(bp + c0), bp1 = __ldg(bp + c0 + 1);
            const float q0 = __ldg(query + g * CDIM + c0);
            const float q1 = __ldg(query + g * CDIM + c0 + 1);
            *(float2*)&sX[g * CDIM + c0]       = make_float2(C[0] + bp0 + q0, C[1] + bp1 + q1);
            *(float2*)&sX[(g + 8) * CDIM + c0] = make_float2(C[2] + bp0 + q0, C[3] + bp1 + q1);
        }
        __syncthreads();

        // ---- Phase 4: LN2 (16 rows, warp per row) -> sAt (bf16) ----
        if (w < 16) {
            const int row = w;
            float4 xv = *(const float4*)&sX[row * CDIM + lane * 4];
            float s1 = xv.x + xv.y + xv.z + xv.w;
            float s2 = xv.x * xv.x + xv.y * xv.y + xv.z * xv.z + xv.w * xv.w;
            s1 = warp_sum(s1);
            s2 = warp_sum(s2);
            float m = s1 * (1.0f / 128.0f);
            float var = s2 * (1.0f / 128.0f) - m * m;
            float rs = rsqrtf(var + LN_EPS);
            float4 gv  = __ldg((const float4*)ln2_g + lane);
            float4 bv2 = __ldg((const float4*)ln2_b + lane);
            *(uint2*)&sAt[row * SAW + lane * 2] = make_uint2(
                bfpack((xv.x - m) * rs * gv.x + bv2.x, (xv.y - m) * rs * gv.y + bv2.y),
                bfpack((xv.z - m) * rs * gv.z + bv2.z, (xv.w - m) * rs * gv.w + bv2.w));
        }
        __syncthreads();

        // ---- Phase 5: f = gelu(ln @ Wf1 + bf1) -> sF (overlays dots) ----
        {
            float C[4] = {0.f, 0.f, 0.f, 0.f};
            #pragma unroll
            for (int ks = 0; ks < 8; ks++) {
                unsigned A4[4];
                ldsm_x4(A4, sAt_u32 + ((ks * 8) << 2) + laneoff);
                uint2 bb2 = __ldg(&g_Wf1B[(ks * 16 + w) * 32 + lane]);
                mma_bf16(C, A4, bb2.x, bb2.y);
            }
            const int c0 = w * 8 + 2 * t;
            const float b10 = __ldg(bf1 + c0), b11 = __ldg(bf1 + c0 + 1);
            float v0 = C[0] + b10, v1 = C[1] + b11;
            float v2 = C[2] + b10, v3 = C[3] + b11;
            v0 = 0.5f * v0 * (1.0f + erff(v0 * 0.70710678118654752f));
            v1 = 0.5f * v1 * (1.0f + erff(v1 * 0.70710678118654752f));
            v2 = 0.5f * v2 * (1.0f + erff(v2 * 0.70710678118654752f));
            v3 = 0.5f * v3 * (1.0f + erff(v3 * 0.70710678118654752f));
            sF[g * SAW + w * 4 + t]       = bfpack(v0, v1);
            sF[(g + 8) * SAW + w * 4 + t] = bfpack(v2, v3);
        }
        __syncthreads();

        // ---- Phase 6: out = x + f @ Wf2 + bf2 ----
        {
            float C[4] = {0.f, 0.f, 0.f, 0.f};
            #pragma unroll
            for (int ks = 0; ks < 8; ks++) {
                unsigned A4[4];
                ldsm_x4(A4, sF_u32 + ((ks * 8) << 2) + laneoff);
                uint2 bb2 = __ldg(&g_Wf2B[(ks * 16 + w) * 32 + lane]);
                mma_bf16(C, A4, bb2.x, bb2.y);
            }
            const int c0 = w * 8 + 2 * t;
            const float b20 = __ldg(bf2 + c0), b21 = __ldg(bf2 + c0 + 1);
            const float x00 = sX[g * CDIM + c0],       x01 = sX[g * CDIM + c0 + 1];
            const float x10 = sX[(g + 8) * CDIM + c0], x11 = sX[(g + 8) * CDIM + c0 + 1];
            float* ob = out + (size_t)b0 * (NTOK * CDIM);
            *(float2*)&ob[g * CDIM + c0] =
                make_float2(C[0] + b20 + x00, C[1] + b21 + x01);
            *(float2*)&ob[(g + 8) * CDIM + c0] =
                make_float2(C[2] + b20 + x10, C[3] + b21 + x11);
        }
    }
}

// ---------------- launch ----------------
extern "C" void kernel_launch(void* const* d_in, const int* in_sizes, int n_in,
                              void* d_out, int out_size)
{
    const float* query = (const float*)d_in[0];
    const float* tgt   = (const float*)d_in[1];
    const float* ln1_g = (const float*)d_in[2];
    const float* ln1_b = (const float*)d_in[3];
    const float* ln2_g = (const float*)d_in[4];
    const float* ln2_b = (const float*)d_in[5];
    const float* Wq    = (const float*)d_in[6];
    const float* bq    = (const float*)d_in[7];
    const float* Wk    = (const float*)d_in[8];
    const float* Wv    = (const float*)d_in[10];
    const float* bv    = (const float*)d_in[11];
    const float* Wp    = (const float*)d_in[12];
    const float* bp    = (const float*)d_in[13];
    const float* Wf1   = (const float*)d_in[14];
    const float* bf1   = (const float*)d_in[15];
    const float* Wf2   = (const float*)d_in[16];
    const float* bf2   = (const float*)d_in[17];
    float* out = (float*)d_out;

    const int B = in_sizes[1] / (LTOK * CDIM);
    const int npairs = B / 2;
    int grid = 296;
    if (grid > npairs) grid = npairs;

    cudaFuncSetAttribute(mega_kernel, cudaFuncAttributeMaxDynamicSharedMemorySize, SM_MEGA_BYTES);

    precompute_kernel<<<72, 256>>>(query, ln1_g, ln1_b, Wq, bq, Wk, Wv, Wp, Wf1, Wf2);
    mega_kernel<<<grid, 512, SM_MEGA_BYTES>>>(
        tgt, query, bv, bp, ln2_g, ln2_b, bf1, bf2, out, npairs);
}

// round 10
// speedup vs baseline: 1.0928x; 1.0928x over previous
#include <cuda_runtime.h>
#include <cuda_fp16.h>
#include <math.h>

#define CDIM   128
#define LTOK   54
#define NTOK   8
#define LN_EPS 1e-5f
#define SAW    68      // smem row stride in f16x2 words (17x16B -> ldmatrix conflict-free)
#define SDW    33      // dots row stride in f16x2 words

// ---------------- device globals (precomputed weights, f16 fragment order) ----------------
__device__ uint2 g_WcB [8 * 24 * 32];   // combined [A_fold | Wv] f16 B-frags
__device__ uint2 g_WpB [8 * 16 * 32];   // Wp  f16 B-frags
__device__ uint2 g_Wf1B[8 * 16 * 32];   // Wf1 f16 B-frags
__device__ uint2 g_Wf2B[8 * 16 * 32];   // Wf2 f16 B-frags

// ---------------- helpers ----------------
__device__ __forceinline__ unsigned hpack(float lo, float hi) {
    __half2 h = __floats2half2_rn(lo, hi);
    return *(unsigned*)&h;
}
__device__ __forceinline__ float2 hunpack(unsigned u) {
    return __half22float2(*(__half2*)&u);
}

// f16 inputs, f32 accumulators (tail GEMMs)
__device__ __forceinline__ void mma_f32(float* c, const unsigned* a, unsigned b0, unsigned b1) {
    asm volatile(
        "mma.sync.aligned.m16n8k16.row.col.f32.f16.f16.f32 "
        "{%0,%1,%2,%3},{%4,%5,%6,%7},{%8,%9},{%0,%1,%2,%3};"
        : "+f"(c[0]), "+f"(c[1]), "+f"(c[2]), "+f"(c[3])
        : "r"(a[0]), "r"(a[1]), "r"(a[2]), "r"(a[3]), "r"(b0), "r"(b1));
}

// f16 inputs, f16 accumulators (GEMM1: 2 regs per tile)
__device__ __forceinline__ void mma_f16(unsigned* c, const unsigned* a, unsigned b0, unsigned b1) {
    asm volatile(
        "mma.sync.aligned.m16n8k16.row.col.f16.f16.f16.f16 "
        "{%0,%1},{%2,%3,%4,%5},{%6,%7},{%0,%1};"
        : "+r"(c[0]), "+r"(c[1])
        : "r"(a[0]), "r"(a[1]), "r"(a[2]), "r"(a[3]), "r"(b0), "r"(b1));
}

__device__ __forceinline__ void ldsm_x4(unsigned* r, unsigned saddr) {
    asm volatile(
        "ldmatrix.sync.aligned.m8n8.x4.shared.b16 {%0,%1,%2,%3}, [%4];"
        : "=r"(r[0]), "=r"(r[1]), "=r"(r[2]), "=r"(r[3]) : "r"(saddr));
}

__device__ __forceinline__ float warp_sum(float v) {
    v += __shfl_xor_sync(0xffffffffu, v, 16);
    v += __shfl_xor_sync(0xffffffffu, v, 8);
    v += __shfl_xor_sync(0xffffffffu, v, 4);
    v += __shfl_xor_sync(0xffffffffu, v, 2);
    v += __shfl_xor_sync(0xffffffffu, v, 1);
    return v;
}

// ---------------- precompute: 72 blocks x 256 threads = 18432 pack items ----------------
__global__ __launch_bounds__(256, 4) void precompute_kernel(
    const float* __restrict__ query,
    const float* __restrict__ ln1_g, const float* __restrict__ ln1_b,
    const float* __restrict__ Wq, const float* __restrict__ bq,
    const float* __restrict__ Wk,
    const float* __restrict__ Wv,
    const float* __restrict__ Wp,
    const float* __restrict__ Wf1,
    const float* __restrict__ Wf2)
{
    __shared__ float s_qn[NTOK * CDIM];
    __shared__ float s_q[NTOK * CDIM];
    const int tid = threadIdx.x;
    const int warp = tid >> 5, lane = tid & 31;

    if (warp < NTOK) {
        const int r = warp;
        float4 xv = *(const float4*)&query[r * CDIM + lane * 4];
        float s1 = xv.x + xv.y + xv.z + xv.w;
        float s2 = xv.x * xv.x + xv.y * xv.y + xv.z * xv.z + xv.w * xv.w;
        s1 = warp_sum(s1);
        s2 = warp_sum(s2);
        float m = s1 * (1.0f / 128.0f);
        float var = s2 * (1.0f / 128.0f) - m * m;
        float rs = rsqrtf(var + LN_EPS);
        float4 g = *(const float4*)&ln1_g[lane * 4];
        float4 be = *(const float4*)&ln1_b[lane * 4];
        float4 o;
        o.x = (xv.x - m) * rs * g.x + be.x;
        o.y = (xv.y - m) * rs * g.y + be.y;
        o.z = (xv.z - m) * rs * g.z + be.z;
        o.w = (xv.w - m) * rs * g.w + be.w;
        *(float4*)&s_qn[r * CDIM + lane * 4] = o;
    }
    __syncthreads();

    #pragma unroll
    for (int j = 0; j < 4; j++) {
        const int idx = tid + j * 256;
        const int t = idx >> 7, o = idx & 127;
        float acc = bq[o];
        #pragma unroll 8
        for (int c = 0; c < CDIM; c++)
            acc += s_qn[t * CDIM + c] * __ldg(Wq + c * CDIM + o);
        s_q[idx] = acc;
    }
    __syncthreads();

    const int gid = blockIdx.x * 256 + tid;
    if (gid < 6144) {
        const int lane2 = gid & 31;
        const int rest = gid >> 5;
        const int nt = rest % 24;
        const int ks = rest / 24;
        const int g = lane2 >> 2, t = lane2 & 3;
        const int c = nt * 8 + g;
        const int k0 = ks * 16 + 2 * t;
        float f0, f1, f2, f3;
        if (c < 64) {
            // A_fold: bk folds to per-column constant -> cancels in softmax
            const int tok = c >> 3, h = c & 7;
            const float* qv = s_q + tok * CDIM + h * 16;
            float a0 = 0.f, a1 = 0.f, a2 = 0.f, a3 = 0.f;
            #pragma unroll
            for (int j = 0; j < 16; j++) {
                const float qj = qv[j];
                a0 += qj * __ldg(Wk + (k0    ) * CDIM + h * 16 + j);
                a1 += qj * __ldg(Wk + (k0 + 1) * CDIM + h * 16 + j);
                a2 += qj * __ldg(Wk + (k0 + 8) * CDIM + h * 16 + j);
                a3 += qj * __ldg(Wk + (k0 + 9) * CDIM + h * 16 + j);
            }
            f0 = 0.25f * a0; f1 = 0.25f * a1; f2 = 0.25f * a2; f3 = 0.25f * a3;
        } else {
            const int cc = c - 64;
            f0 = __ldg(Wv + (k0    ) * CDIM + cc);
            f1 = __ldg(Wv + (k0 + 1) * CDIM + cc);
            f2 = __ldg(Wv + (k0 + 8) * CDIM + cc);
            f3 = __ldg(Wv + (k0 + 9) * CDIM + cc);
        }
        g_WcB[gid] = make_uint2(hpack(f0, f1), hpack(f2, f3));
    } else {
        const int r = (gid - 6144) & 4095;
        const int m = (gid - 6144) >> 12;
        const int lane2 = r & 31;
        const int rest = r >> 5;
        const int nt = rest & 15;
        const int ks = rest >> 4;
        const int g = lane2 >> 2, t = lane2 & 3;
        const int c = nt * 8 + g;
        const int k0 = ks * 16 + 2 * t;
        const float* W = (m == 0) ? Wp : (m == 1) ? Wf1 : Wf2;
        uint2 v = make_uint2(
            hpack(__ldg(W + k0 * CDIM + c), __ldg(W + (k0 + 1) * CDIM + c)),
            hpack(__ldg(W + (k0 + 8) * CDIM + c), __ldg(W + (k0 + 9) * CDIM + c)));
        if (m == 0)      g_WpB [r] = v;
        else if (m == 1) g_Wf1B[r] = v;
        else             g_Wf2B[r] = v;
    }
}

// ---------------- persistent megakernel: 512 threads, 2 blocks/SM ----------------
// smem layout (4B words):
//   sA  [128][SAW] f16x2 : tgt (2x64 rows) -> V overwrite     8704 w
//   sB  [6144]     uint2 : GEMM1 B-frags (staged ONCE)        12288 w
//   sDb [108][SDW] f16x2 : dots (f16); sF overlays here       3564 w
//   sAt [16][SAW]  f16x2 : attn out / LN2 out                 1088 w
//   sX  [16][128]  fp32  : residual x                         2048 w
#define W_A   (128 * SAW)
#define W_B   (6144 * 2)
#define W_D   (108 * SDW)
#define W_AT  (16 * SAW)
#define W_X   (16 * 128)
#define OFF_B  (W_A)
#define OFF_D  (W_A + W_B)
#define OFF_AT (W_A + W_B + W_D)
#define OFF_X  (W_A + W_B + W_D + W_AT)
#define SM_MEGA_BYTES ((W_A + W_B + W_D + W_AT + W_X) * 4)

__global__ __launch_bounds__(512, 2) void mega_kernel(
    const float* __restrict__ tgt,
    const float* __restrict__ query,
    const float* __restrict__ bv,
    const float* __restrict__ bp,
    const float* __restrict__ ln2_g, const float* __restrict__ ln2_b,
    const float* __restrict__ bf1, const float* __restrict__ bf2,
    float* __restrict__ out, int npairs)
{
    extern __shared__ unsigned smw[];
    unsigned* sA  = smw;
    uint2*    sB  = (uint2*)(smw + OFF_B);
    unsigned* sDb = smw + OFF_D;
    unsigned* sF  = smw + OFF_D;          // overlays dots (dead when sF live)
    unsigned* sAt = smw + OFF_AT;
    float*    sX  = (float*)(smw + OFF_X);

    const int tid = threadIdx.x;
    const int w = tid >> 5, lane = tid & 31;
    const int g = lane >> 2, t = lane & 3;

    const unsigned sA_u32  = (unsigned)__cvta_generic_to_shared(sA);
    const unsigned sAt_u32 = (unsigned)__cvta_generic_to_shared(sAt);
    const unsigned sF_u32  = (unsigned)__cvta_generic_to_shared(sF);
    const unsigned laneoff = (((lane & 15) * SAW + (lane >> 4) * 4) << 2);

    // ---- stage GEMM1 B-fragments ONCE per block ----
    {
        const uint4* src = (const uint4*)g_WcB;
        uint4* dst = (uint4*)sB;
        #pragma unroll
        for (int i = 0; i < 6; i++)
            dst[tid + i * 512] = __ldg(src + tid + i * 512);
    }

    for (int pair = blockIdx.x; pair < npairs; pair += gridDim.x) {
        const int b0 = pair * 2;
        __syncthreads();   // protect sA / sDb(sF) reuse across iterations

        // ---- Phase 0: stage tgt (2 batches, 108 rows) as f16 ----
        {
            const float4* gt = (const float4*)(tgt + (size_t)b0 * (LTOK * CDIM));
            #pragma unroll
            for (int i0 = 0; i0 < 7; i0++) {
                const int i = tid + i0 * 512;
                if (i < 2 * LTOK * 32) {
                    const int row = i >> 5, c4 = i & 31;
                    float4 v = __ldg(gt + i);
                    const int bb = (row >= LTOK) ? 1 : 0;
                    const int r = row - bb * LTOK;
                    *(uint2*)&sA[(bb * 64 + r) * SAW + c4 * 2] =
                        make_uint2(hpack(v.x, v.y), hpack(v.z, v.w));
                }
            }
        }
        __syncthreads();

        // ---- Phase 1: GEMM1 merged single pass (f16 accum): 2m x 6n per warp ----
        //      [128(2x54),128] @ [128,192] -> dots (nt<8) | V (nt 8..23)
        {
            const int a = w & 3;          // m-tile pair {2a, 2a+1}
            const int e = w >> 2;         // n-group: tiles e*6 .. e*6+5
            unsigned C[2][6][2];
            #pragma unroll
            for (int m = 0; m < 2; m++)
                #pragma unroll
                for (int n = 0; n < 6; n++) {
                    C[m][n][0] = 0u; C[m][n][1] = 0u;
                }

            const int bbase = e * 6;
            #pragma unroll 2
            for (int ks = 0; ks < 8; ks++) {
                unsigned A0[4], A1[4];
                ldsm_x4(A0, sA_u32 + (((a * 2    ) * 16 * SAW + ks * 8) << 2) + laneoff);
                ldsm_x4(A1, sA_u32 + (((a * 2 + 1) * 16 * SAW + ks * 8) << 2) + laneoff);
                const uint2* brow = &sB[(ks * 24 + bbase) * 32 + lane];
                #pragma unroll
                for (int n = 0; n < 6; n++) {
                    const uint2 B = brow[n * 32];
                    mma_f16(C[0][n], A0, B.x, B.y);
                    mma_f16(C[1][n], A1, B.x, B.y);
                }
            }
            __syncthreads();   // ALL A reads done before V overwrites sA

            #pragma unroll
            for (int m = 0; m < 2; m++) {
                const int r1 = (a * 2 + m) * 16 + g;   // global row 0..127
                const int bb = r1 >> 6, rl = r1 & 63;
                #pragma unroll
                for (int n = 0; n < 6; n++) {
                    const int nt = bbase + n;
                    if (nt < 8) {
                        const int wrd = nt * 4 + t;
                        unsigned* d0 = sDb + (bb * LTOK + rl) * SDW + wrd;
                        if (rl < LTOK)     d0[0]       = C[m][n][0];
                        if (rl + 8 < LTOK) d0[8 * SDW] = C[m][n][1];
                    } else {
                        const int wrd = (nt - 8) * 4 + t;
                        unsigned* v0 = sA + r1 * SAW + wrd;
                        if (rl < LTOK)     v0[0]       = C[m][n][0];
                        if (rl + 8 < LTOK) v0[8 * SAW] = C[m][n][1];
                    }
                }
            }
        }
        __syncthreads();

        // ---- Phase 2: softmax + AV: 512 tasks (2b x 8tok x 8head x 4quarter) ----
        {
            const int bb = tid >> 8;
            const int rest = tid & 255;
            const int th = rest >> 2, qt = rest & 3;
            const int tok = th >> 3, h = th & 7;
            const int ridx = (tok < 2) ? tok : (tok - 2);
            const int hb = ridx / 3, wb = ridx % 3;
            const int l0 = hb * 27 + wb * 3;
            int ls[9];
            #pragma unroll
            for (int d = 0; d < 9; d++) ls[d] = l0 + (d / 3) * 9 + (d % 3);

            const int dw = th >> 1, dh = th & 1;
            float dv[9];
            float mx = -1e30f;
            #pragma unroll
            for (int d = 0; d < 9; d++) {
                float2 p = hunpack(sDb[(bb * LTOK + ls[d]) * SDW + dw]);
                dv[d] = dh ? p.y : p.x;
                mx = fmaxf(mx, dv[d]);
            }
            float ssum = 0.0f;
            #pragma unroll
            for (int d = 0; d < 9; d++) {
                dv[d] = __expf(dv[d] - mx);
                ssum += dv[d];
            }
            const float inv = 1.0f / ssum;
            float acc[4] = {0.f, 0.f, 0.f, 0.f};
            #pragma unroll
            for (int d = 0; d < 9; d++) {
                const uint2 vv = *(const uint2*)&sA[(bb * 64 + ls[d]) * SAW + h * 8 + qt * 2];
                float2 p;
                p = hunpack(vv.x); acc[0] += dv[d] * p.x; acc[1] += dv[d] * p.y;
                p = hunpack(vv.y); acc[2] += dv[d] * p.x; acc[3] += dv[d] * p.y;
            }
            const int cb = h * 16 + qt * 4;
            const float b0v = __ldg(bv + cb),     b1v = __ldg(bv + cb + 1);
            const float b2v = __ldg(bv + cb + 2), b3v = __ldg(bv + cb + 3);
            *(uint2*)&sAt[(bb * 8 + tok) * SAW + h * 8 + qt * 2] = make_uint2(
                hpack(acc[0] * inv + b0v, acc[1] * inv + b1v),
                hpack(acc[2] * inv + b2v, acc[3] * inv + b3v));
        }
        __syncthreads();

        // ===== tail: M=16 x 128 GEMMs (f32 accum), warp w owns n-tile w =====

        // ---- Phase 3: proj: x = query + attn @ Wp + bp -> sX ----
        {
            float C[4] = {0.f, 0.f, 0.f, 0.f};
            #pragma unroll
            for (int ks = 0; ks < 8; ks++) {
                unsigned A4[4];
                ldsm_x4(A4, sAt_u32 + ((ks * 8) << 2) + laneoff);
                uint2 bb2 = __ldg(&g_WpB[(ks * 16 + w) * 32 + lane]);
                mma_f32(C, A4, bb2.x, bb2.y);
            }
            const int c0 = w * 8 + 2 * t;
            const float bp0 = __ldg(bp + c0), bp1 = __ldg(bp + c0 + 1);
            const float q0 = __ldg(query + g * CDIM + c0);
            const float q1 = __ldg(query + g * CDIM + c0 + 1);
            *(float2*)&sX[g * CDIM + c0]       = make_float2(C[0] + bp0 + q0, C[1] + bp1 + q1);
            *(float2*)&sX[(g + 8) * CDIM + c0] = make_float2(C[2] + bp0 + q0, C[3] + bp1 + q1);
        }
        __syncthreads();

        // ---- Phase 4: LN2 (16 rows, warp per row) -> sAt (f16) ----
        if (w < 16) {
            const int row = w;
            float4 xv = *(const float4*)&sX[row * CDIM + lane * 4];
            float s1 = xv.x + xv.y + xv.z + xv.w;
            float s2 = xv.x * xv.x + xv.y * xv.y + xv.z * xv.z + xv.w * xv.w;
            s1 = warp_sum(s1);
            s2 = warp_sum(s2);
            float m = s1 * (1.0f / 128.0f);
            float var = s2 * (1.0f / 128.0f) - m * m;
            float rs = rsqrtf(var + LN_EPS);
            float4 gv  = __ldg((const float4*)ln2_g + lane);
            float4 bv2 = __ldg((const float4*)ln2_b + lane);
            *(uint2*)&sAt[row * SAW + lane * 2] = make_uint2(
                hpack((xv.x - m) * rs * gv.x + bv2.x, (xv.y - m) * rs * gv.y + bv2.y),
                hpack((xv.z - m) * rs * gv.z + bv2.z, (xv.w - m) * rs * gv.w + bv2.w));
        }
        __syncthreads();

        // ---- Phase 5: f = gelu(ln @ Wf1 + bf1) -> sF (overlays dots) ----
        {
            float C[4] = {0.f, 0.f, 0.f, 0.f};
            #pragma unroll
            for (int ks = 0; ks < 8; ks++) {
                unsigned A4[4];
                ldsm_x4(A4, sAt_u32 + ((ks * 8) << 2) + laneoff);
                uint2 bb2 = __ldg(&g_Wf1B[(ks * 16 + w) * 32 + lane]);
                mma_f32(C, A4, bb2.x, bb2.y);
            }
            const int c0 = w * 8 + 2 * t;
            const float b10 = __ldg(bf1 + c0), b11 = __ldg(bf1 + c0 + 1);
            float v0 = C[0] + b10, v1 = C[1] + b11;
            float v2 = C[2] + b10, v3 = C[3] + b11;
            v0 = 0.5f * v0 * (1.0f + erff(v0 * 0.70710678118654752f));
            v1 = 0.5f * v1 * (1.0f + erff(v1 * 0.70710678118654752f));
            v2 = 0.5f * v2 * (1.0f + erff(v2 * 0.70710678118654752f));
            v3 = 0.5f * v3 * (1.0f + erff(v3 * 0.70710678118654752f));
            sF[g * SAW + w * 4 + t]       = hpack(v0, v1);
            sF[(g + 8) * SAW + w * 4 + t] = hpack(v2, v3);
        }
        __syncthreads();

        // ---- Phase 6: out = x + f @ Wf2 + bf2 ----
        {
            float C[4] = {0.f, 0.f, 0.f, 0.f};
            #pragma unroll
            for (int ks = 0; ks < 8; ks++) {
                unsigned A4[4];
                ldsm_x4(A4, sF_u32 + ((ks * 8) << 2) + laneoff);
                uint2 bb2 = __ldg(&g_Wf2B[(ks * 16 + w) * 32 + lane]);
                mma_f32(C, A4, bb2.x, bb2.y);
            }
            const int c0 = w * 8 + 2 * t;
            const float b20 = __ldg(bf2 + c0), b21 = __ldg(bf2 + c0 + 1);
            const float x00 = sX[g * CDIM + c0],       x01 = sX[g * CDIM + c0 + 1];
            const float x10 = sX[(g + 8) * CDIM + c0], x11 = sX[(g + 8) * CDIM + c0 + 1];
            float* ob = out + (size_t)b0 * (NTOK * CDIM);
            *(float2*)&ob[g * CDIM + c0] =
                make_float2(C[0] + b20 + x00, C[1] + b21 + x01);
            *(float2*)&ob[(g + 8) * CDIM + c0] =
                make_float2(C[2] + b20 + x10, C[3] + b21 + x11);
        }
    }
}

// ---------------- launch ----------------
extern "C" void kernel_launch(void* const* d_in, const int* in_sizes, int n_in,
                              void* d_out, int out_size)
{
    const float* query = (const float*)d_in[0];
    const float* tgt   = (const float*)d_in[1];
    const float* ln1_g = (const float*)d_in[2];
    const float* ln1_b = (const float*)d_in[3];
    const float* ln2_g = (const float*)d_in[4];
    const float* ln2_b = (const float*)d_in[5];
    const float* Wq    = (const float*)d_in[6];
    const float* bq    = (const float*)d_in[7];
    const float* Wk    = (const float*)d_in[8];
    const float* Wv    = (const float*)d_in[10];
    const float* bv    = (const float*)d_in[11];
    const float* Wp    = (const float*)d_in[12];
    const float* bp    = (const float*)d_in[13];
    const float* Wf1   = (const float*)d_in[14];
    const float* bf1   = (const float*)d_in[15];
    const float* Wf2   = (const float*)d_in[16];
    const float* bf2   = (const float*)d_in[17];
    float* out = (float*)d_out;

    const int B = in_sizes[1] / (LTOK * CDIM);
    const int npairs = B / 2;
    int grid = 296;
    if (grid > npairs) grid = npairs;

    cudaFuncSetAttribute(mega_kernel, cudaFuncAttributeMaxDynamicSharedMemorySize, SM_MEGA_BYTES);

    precompute_kernel<<<72, 256>>>(query, ln1_g, ln1_b, Wq, bq, Wk, Wv, Wp, Wf1, Wf2);
    mega_kernel<<<grid, 512, SM_MEGA_BYTES>>>(
        tgt, query, bv, bp, ln2_g, ln2_b, bf1, bf2, out, npairs);
}

// round 12
// speedup vs baseline: 1.1813x; 1.0810x over previous
#include <cuda_runtime.h>
#include <cuda_fp16.h>
#include <math.h>

#define CDIM   128
#define LTOK   54
#define NTOK   8
#define LN_EPS 1e-5f
#define SAW    68      // smem row stride in f16x2 words (17x16B -> ldmatrix conflict-free)
#define SDW    33      // dots row stride in f16x2 words
#define SXW    66      // x (f16) row stride in f16x2 words (EVEN: uint2-aligned rows)

// ---------------- device globals (precomputed weights, f16 fragment order) ----------------
__device__ uint2 g_WcB [8 * 24 * 32];   // combined [A_fold | Wv] f16 B-frags
__device__ uint2 g_WpB [8 * 16 * 32];   // Wp  f16 B-frags
__device__ uint2 g_Wf1B[8 * 16 * 32];   // Wf1 f16 B-frags
__device__ uint2 g_Wf2B[8 * 16 * 32];   // Wf2 f16 B-frags

// ---------------- helpers ----------------
__device__ __forceinline__ unsigned hpack(float lo, float hi) {
    __half2 h = __floats2half2_rn(lo, hi);
    return *(unsigned*)&h;
}
__device__ __forceinline__ float2 hunpack(unsigned u) {
    return __half22float2(*(__half2*)&u);
}

__device__ __forceinline__ void mma_f32(float* c, const unsigned* a, unsigned b0, unsigned b1) {
    asm volatile(
        "mma.sync.aligned.m16n8k16.row.col.f32.f16.f16.f32 "
        "{%0,%1,%2,%3},{%4,%5,%6,%7},{%8,%9},{%0,%1,%2,%3};"
        : "+f"(c[0]), "+f"(c[1]), "+f"(c[2]), "+f"(c[3])
        : "r"(a[0]), "r"(a[1]), "r"(a[2]), "r"(a[3]), "r"(b0), "r"(b1));
}

__device__ __forceinline__ void mma_f16(unsigned* c, const unsigned* a, unsigned b0, unsigned b1) {
    asm volatile(
        "mma.sync.aligned.m16n8k16.row.col.f16.f16.f16.f16 "
        "{%0,%1},{%2,%3,%4,%5},{%6,%7},{%0,%1};"
        : "+r"(c[0]), "+r"(c[1])
        : "r"(a[0]), "r"(a[1]), "r"(a[2]), "r"(a[3]), "r"(b0), "r"(b1));
}

__device__ __forceinline__ void ldsm_x4(unsigned* r, unsigned saddr) {
    asm volatile(
        "ldmatrix.sync.aligned.m8n8.x4.shared.b16 {%0,%1,%2,%3}, [%4];"
        : "=r"(r[0]), "=r"(r[1]), "=r"(r[2]), "=r"(r[3]) : "r"(saddr));
}

__device__ __forceinline__ float warp_sum(float v) {
    v += __shfl_xor_sync(0xffffffffu, v, 16);
    v += __shfl_xor_sync(0xffffffffu, v, 8);
    v += __shfl_xor_sync(0xffffffffu, v, 4);
    v += __shfl_xor_sync(0xffffffffu, v, 2);
    v += __shfl_xor_sync(0xffffffffu, v, 1);
    return v;
}

// ---------------- precompute: 72 blocks x 256 threads = 18432 pack items ----------------
__global__ __launch_bounds__(256, 4) void precompute_kernel(
    const float* __restrict__ query,
    const float* __restrict__ ln1_g, const float* __restrict__ ln1_b,
    const float* __restrict__ Wq, const float* __restrict__ bq,
    const float* __restrict__ Wk,
    const float* __restrict__ Wv,
    const float* __restrict__ Wp,
    const float* __restrict__ Wf1,
    const float* __restrict__ Wf2)
{
    __shared__ float s_qn[NTOK * CDIM];
    __shared__ float s_q[NTOK * CDIM];
    const int tid = threadIdx.x;
    const int warp = tid >> 5, lane = tid & 31;

    if (warp < NTOK) {
        const int r = warp;
        float4 xv = *(const float4*)&query[r * CDIM + lane * 4];
        float s1 = xv.x + xv.y + xv.z + xv.w;
        float s2 = xv.x * xv.x + xv.y * xv.y + xv.z * xv.z + xv.w * xv.w;
        s1 = warp_sum(s1);
        s2 = warp_sum(s2);
        float m = s1 * (1.0f / 128.0f);
        float var = s2 * (1.0f / 128.0f) - m * m;
        float rs = rsqrtf(var + LN_EPS);
        float4 g = *(const float4*)&ln1_g[lane * 4];
        float4 be = *(const float4*)&ln1_b[lane * 4];
        float4 o;
        o.x = (xv.x - m) * rs * g.x + be.x;
        o.y = (xv.y - m) * rs * g.y + be.y;
        o.z = (xv.z - m) * rs * g.z + be.z;
        o.w = (xv.w - m) * rs * g.w + be.w;
        *(float4*)&s_qn[r * CDIM + lane * 4] = o;
    }
    __syncthreads();

    #pragma unroll
    for (int j = 0; j < 4; j++) {
        const int idx = tid + j * 256;
        const int t = idx >> 7, o = idx & 127;
        float acc = bq[o];
        #pragma unroll 8
        for (int c = 0; c < CDIM; c++)
            acc += s_qn[t * CDIM + c] * __ldg(Wq + c * CDIM + o);
        s_q[idx] = acc;
    }
    __syncthreads();

    const int gid = blockIdx.x * 256 + tid;
    if (gid < 6144) {
        const int lane2 = gid & 31;
        const int rest = gid >> 5;
        const int nt = rest % 24;
        const int ks = rest / 24;
        const int g = lane2 >> 2, t = lane2 & 3;
        const int c = nt * 8 + g;
        const int k0 = ks * 16 + 2 * t;
        float f0, f1, f2, f3;
        if (c < 64) {
            // A_fold: bk folds to per-column constant -> cancels in softmax
            const int tok = c >> 3, h = c & 7;
            const float* qv = s_q + tok * CDIM + h * 16;
            float a0 = 0.f, a1 = 0.f, a2 = 0.f, a3 = 0.f;
            #pragma unroll
            for (int j = 0; j < 16; j++) {
                const float qj = qv[j];
                a0 += qj * __ldg(Wk + (k0    ) * CDIM + h * 16 + j);
                a1 += qj * __ldg(Wk + (k0 + 1) * CDIM + h * 16 + j);
                a2 += qj * __ldg(Wk + (k0 + 8) * CDIM + h * 16 + j);
                a3 += qj * __ldg(Wk + (k0 + 9) * CDIM + h * 16 + j);
            }
            f0 = 0.25f * a0; f1 = 0.25f * a1; f2 = 0.25f * a2; f3 = 0.25f * a3;
        } else {
            const int cc = c - 64;
            f0 = __ldg(Wv + (k0    ) * CDIM + cc);
            f1 = __ldg(Wv + (k0 + 1) * CDIM + cc);
            f2 = __ldg(Wv + (k0 + 8) * CDIM + cc);
            f3 = __ldg(Wv + (k0 + 9) * CDIM + cc);
        }
        g_WcB[gid] = make_uint2(hpack(f0, f1), hpack(f2, f3));
    } else {
        const int r = (gid - 6144) & 4095;
        const int m = (gid - 6144) >> 12;
        const int lane2 = r & 31;
        const int rest = r >> 5;
        const int nt = rest & 15;
        const int ks = rest >> 4;
        const int g = lane2 >> 2, t = lane2 & 3;
        const int c = nt * 8 + g;
        const int k0 = ks * 16 + 2 * t;
        const float* W = (m == 0) ? Wp : (m == 1) ? Wf1 : Wf2;
        uint2 v = make_uint2(
            hpack(__ldg(W + k0 * CDIM + c), __ldg(W + (k0 + 1) * CDIM + c)),
            hpack(__ldg(W + (k0 + 8) * CDIM + c), __ldg(W + (k0 + 9) * CDIM + c)));
        if (m == 0)      g_WpB [r] = v;
        else if (m == 1) g_Wf1B[r] = v;
        else             g_Wf2B[r] = v;
    }
}

// ---------------- persistent megakernel: 512 threads, 2 blocks/SM ----------------
// Processes a QUAD (4 batches = 2 pairs) per loop iteration.
// smem layout (4B words):
//   sA  [108(pad112)][SAW] f16x2 : tgt packed -> V overwrite   7616 w  (30.5KB)
//   sB  [6144] uint2 : GEMM1 B-frags (staged ONCE)             12288 w (49.2KB)
//   sDb [108][SDW] f16x2 : dots; sF[32][SAW] overlays          3564 w  (14.3KB)
//   sAt [32][SAW] f16x2  : attn out (2 pairs) / LN2 out        2176 w  (8.7KB)
//   sXh [32][SXW] f16x2  : x (f16 copy, LN2 stats only)        2112 w  (8.4KB)
#define W_A   (112 * SAW)
#define W_B   (6144 * 2)
#define W_D   (108 * SDW)
#define W_AT  (32 * SAW)
#define W_XH  (32 * SXW)
#define OFF_B  (W_A)
#define OFF_D  (W_A + W_B)
#define OFF_AT (W_A + W_B + W_D)
#define OFF_XH (W_A + W_B + W_D + W_AT)
#define SM_MEGA_BYTES ((W_A + W_B + W_D + W_AT + W_XH) * 4)

__global__ __launch_bounds__(512, 2) void mega_kernel(
    const float* __restrict__ tgt,
    const float* __restrict__ query,
    const float* __restrict__ bv,
    const float* __restrict__ bp,
    const float* __restrict__ ln2_g, const float* __restrict__ ln2_b,
    const float* __restrict__ bf1, const float* __restrict__ bf2,
    float* __restrict__ out, int nquads)
{
    extern __shared__ unsigned smw[];
    unsigned* sA  = smw;
    uint2*    sB  = (uint2*)(smw + OFF_B);
    unsigned* sDb = smw + OFF_D;
    unsigned* sF  = smw + OFF_D;          // overlays dots (dead when sF live)
    unsigned* sAt = smw + OFF_AT;
    unsigned* sXh = smw + OFF_XH;

    const int tid = threadIdx.x;
    const int w = tid >> 5, lane = tid & 31;
    const int g = lane >> 2, t = lane & 3;

    const unsigned sA_u32  = (unsigned)__cvta_generic_to_shared(sA);
    const unsigned sAt_u32 = (unsigned)__cvta_generic_to_shared(sAt);
    const unsigned sF_u32  = (unsigned)__cvta_generic_to_shared(sF);
    const unsigned laneoff = (((lane & 15) * SAW + (lane >> 4) * 4) << 2);

    // ---- stage GEMM1 B-fragments ONCE per block ----
    {
        const uint4* src = (const uint4*)g_WcB;
        uint4* dst = (uint4*)sB;
        #pragma unroll
        for (int i = 0; i < 6; i++)
            dst[tid + i * 512] = __ldg(src + tid + i * 512);
    }

    for (int quad = blockIdx.x; quad < nquads; quad += gridDim.x) {
        const int b0q = quad * 4;

        // ======== per-pair attention: j = 0, 1 ========
        #pragma unroll 1
        for (int j = 0; j < 2; j++) {
            __syncthreads();   // guard sA / dots reuse

            // ---- stage tgt (2 batches, 108 packed rows) as f16 ----
            {
                const float4* gt = (const float4*)(tgt + (size_t)(b0q + j * 2) * (LTOK * CDIM));
                #pragma unroll
                for (int i0 = 0; i0 < 7; i0++) {
                    const int i = tid + i0 * 512;
                    if (i < 2 * LTOK * 32) {
                        const int row = i >> 5, c4 = i & 31;
                        float4 v = __ldg(gt + i);
                        *(uint2*)&sA[row * SAW + c4 * 2] =
                            make_uint2(hpack(v.x, v.y), hpack(v.z, v.w));
                    }
                }
            }
            __syncthreads();

            // ---- GEMM1 (f16 accum): 2m x 6n per warp; [112(108),128]@[128,192] ----
            {
                const int a = w & 3;          // m-tile pair {2a, 2a+1}
                const int e = w >> 2;         // n-group: tiles e*6 .. e*6+5
                unsigned C[2][6][2];
                #pragma unroll
                for (int m = 0; m < 2; m++)
                    #pragma unroll
                    for (int n = 0; n < 6; n++) {
                        C[m][n][0] = 0u; C[m][n][1] = 0u;
                    }

                const int bbase = e * 6;
                #pragma unroll 2
                for (int ks = 0; ks < 8; ks++) {
                    unsigned A0[4], A1[4];
                    ldsm_x4(A0, sA_u32 + (((a * 2    ) * 16 * SAW + ks * 8) << 2) + laneoff);
                    ldsm_x4(A1, sA_u32 + (((a * 2 + 1) * 16 * SAW + ks * 8) << 2) + laneoff);
                    const uint2* brow = &sB[(ks * 24 + bbase) * 32 + lane];
                    #pragma unroll
                    for (int n = 0; n < 6; n++) {
                        const uint2 B = brow[n * 32];
                        mma_f16(C[0][n], A0, B.x, B.y);
                        mma_f16(C[1][n], A1, B.x, B.y);
                    }
                }
                __syncthreads();   // ALL A reads done before V overwrites sA

                #pragma unroll
                for (int m = 0; m < 2; m++) {
                    const int rA = (a * 2 + m) * 16 + g;   // packed row (>=108 invalid)
                    const int rB = rA + 8;
                    #pragma unroll
                    for (int n = 0; n < 6; n++) {
                        const int nt = bbase + n;
                        if (nt < 8) {
                            const int wrd = nt * 4 + t;
                            if (rA < 108) sDb[rA * SDW + wrd] = C[m][n][0];
                            if (rB < 108) sDb[rB * SDW + wrd] = C[m][n][1];
                        } else {
                            const int wrd = (nt - 8) * 4 + t;
                            if (rA < 108) sA[rA * SAW + wrd] = C[m][n][0];
                            if (rB < 108) sA[rB * SAW + wrd] = C[m][n][1];
                        }
                    }
                }
            }
            __syncthreads();

            // ---- softmax + AV: 512 tasks (2b x 8tok x 8head x 4quarter) ----
            {
                const int bb = tid >> 8;
                const int rest = tid & 255;
                const int th = rest >> 2, qt = rest & 3;
                const int tok = th >> 3, h = th & 7;
                const int ridx = (tok < 2) ? tok : (tok - 2);
                const int hb = ridx / 3, wb = ridx % 3;
                const int l0 = hb * 27 + wb * 3;
                int ls[9];
                #pragma unroll
                for (int d = 0; d < 9; d++) ls[d] = bb * LTOK + l0 + (d / 3) * 9 + (d % 3);

                const int dw = th >> 1, dh = th & 1;
                float dv[9];
                float mx = -1e30f;
                #pragma unroll
                for (int d = 0; d < 9; d++) {
                    float2 p = hunpack(sDb[ls[d] * SDW + dw]);
                    dv[d] = dh ? p.y : p.x;
                    mx = fmaxf(mx, dv[d]);
                }
                float ssum = 0.0f;
                #pragma unroll
                for (int d = 0; d < 9; d++) {
                    dv[d] = __expf(dv[d] - mx);
                    ssum += dv[d];
                }
                const float inv = 1.0f / ssum;
                float acc[4] = {0.f, 0.f, 0.f, 0.f};
                #pragma unroll
                for (int d = 0; d < 9; d++) {
                    const uint2 vv = *(const uint2*)&sA[ls[d] * SAW + h * 8 + qt * 2];
                    float2 p;
                    p = hunpack(vv.x); acc[0] += dv[d] * p.x; acc[1] += dv[d] * p.y;
                    p = hunpack(vv.y); acc[2] += dv[d] * p.x; acc[3] += dv[d] * p.y;
                }
                const int cb = h * 16 + qt * 4;
                const float b0v = __ldg(bv + cb),     b1v = __ldg(bv + cb + 1);
                const float b2v = __ldg(bv + cb + 2), b3v = __ldg(bv + cb + 3);
                *(uint2*)&sAt[(j * 16 + bb * 8 + tok) * SAW + h * 8 + qt * 2] = make_uint2(
                    hpack(acc[0] * inv + b0v, acc[1] * inv + b1v),
                    hpack(acc[2] * inv + b2v, acc[3] * inv + b3v));
            }
        }
        __syncthreads();

        // ===== tail: M=32 x 128 GEMMs over the quad; warp w owns n-tile w =====
        const int c0 = w * 8 + 2 * t;

        // ---- proj: x = query + attn @ Wp + bp ; x kept fp32 in regs, f16 copy to sXh ----
        float xC[2][4];
        {
            #pragma unroll
            for (int m = 0; m < 2; m++)
                #pragma unroll
                for (int q = 0; q < 4; q++) xC[m][q] = 0.0f;
            #pragma unroll
            for (int ks = 0; ks < 8; ks++) {
                uint2 bb2 = __ldg(&g_WpB[(ks * 16 + w) * 32 + lane]);
                #pragma unroll
                for (int m = 0; m < 2; m++) {
                    unsigned A4[4];
                    ldsm_x4(A4, sAt_u32 + (((m * 16) * SAW + ks * 8) << 2) + laneoff);
                    mma_f32(xC[m], A4, bb2.x, bb2.y);
                }
            }
            const float bp0 = __ldg(bp + c0), bp1 = __ldg(bp + c0 + 1);
            const float q0 = __ldg(query + g * CDIM + c0);
            const float q1 = __ldg(query + g * CDIM + c0 + 1);
            #pragma unroll
            for (int m = 0; m < 2; m++) {
                xC[m][0] += bp0 + q0; xC[m][1] += bp1 + q1;
                xC[m][2] += bp0 + q0; xC[m][3] += bp1 + q1;
                sXh[(m * 16 + g    ) * SXW + w * 4 + t] = hpack(xC[m][0], xC[m][1]);
                sXh[(m * 16 + g + 8) * SXW + w * 4 + t] = hpack(xC[m][2], xC[m][3]);
            }
        }
        __syncthreads();

        // ---- LN2 (32 rows, warp per row x2) -> sAt (f16, overwrite) ----
        {
            const float4 gv  = __ldg((const float4*)ln2_g + lane);
            const float4 bv2 = __ldg((const float4*)ln2_b + lane);
            #pragma unroll
            for (int rr = w; rr < 32; rr += 16) {
                uint2 xu = *(const uint2*)&sXh[rr * SXW + lane * 2];
                float2 xa = hunpack(xu.x), xb = hunpack(xu.y);
                float s1 = xa.x + xa.y + xb.x + xb.y;
                float s2 = xa.x * xa.x + xa.y * xa.y + xb.x * xb.x + xb.y * xb.y;
                s1 = warp_sum(s1);
                s2 = warp_sum(s2);
                float m = s1 * (1.0f / 128.0f);
                float var = s2 * (1.0f / 128.0f) - m * m;
                float rs = rsqrtf(var + LN_EPS);
                *(uint2*)&sAt[rr * SAW + lane * 2] = make_uint2(
                    hpack((xa.x - m) * rs * gv.x + bv2.x, (xa.y - m) * rs * gv.y + bv2.y),
                    hpack((xb.x - m) * rs * gv.z + bv2.z, (xb.y - m) * rs * gv.w + bv2.w));
            }
        }
        __syncthreads();

        // ---- f = gelu(ln @ Wf1 + bf1) -> sF (overlays dots) ----
        {
            float C[2][4];
            #pragma unroll
            for (int m = 0; m < 2; m++)
                #pragma unroll
                for (int q = 0; q < 4; q++) C[m][q] = 0.0f;
            #pragma unroll
            for (int ks = 0; ks < 8; ks++) {
                uint2 bb2 = __ldg(&g_Wf1B[(ks * 16 + w) * 32 + lane]);
                #pragma unroll
                for (int m = 0; m < 2; m++) {
                    unsigned A4[4];
                    ldsm_x4(A4, sAt_u32 + (((m * 16) * SAW + ks * 8) << 2) + laneoff);
                    mma_f32(C[m], A4, bb2.x, bb2.y);
                }
            }
            const float b10 = __ldg(bf1 + c0), b11 = __ldg(bf1 + c0 + 1);
            #pragma unroll
            for (int m = 0; m < 2; m++) {
                float v0 = C[m][0] + b10, v1 = C[m][1] + b11;
                float v2 = C[m][2] + b10, v3 = C[m][3] + b11;
                v0 = 0.5f * v0 * (1.0f + erff(v0 * 0.70710678118654752f));
                v1 = 0.5f * v1 * (1.0f + erff(v1 * 0.70710678118654752f));
                v2 = 0.5f * v2 * (1.0f + erff(v2 * 0.70710678118654752f));
                v3 = 0.5f * v3 * (1.0f + erff(v3 * 0.70710678118654752f));
                sF[(m * 16 + g    ) * SAW + w * 4 + t] = hpack(v0, v1);
                sF[(m * 16 + g + 8) * SAW + w * 4 + t] = hpack(v2, v3);
            }
        }
        __syncthreads();

        // ---- out = x + f @ Wf2 + bf2  (x from regs, fp32) ----
        {
            float C[2][4];
            #pragma unroll
            for (int m = 0; m < 2; m++)
                #pragma unroll
                for (int q = 0; q < 4; q++) C[m][q] = 0.0f;
            #pragma unroll
            for (int ks = 0; ks < 8; ks++) {
                uint2 bb2 = __ldg(&g_Wf2B[(ks * 16 + w) * 32 + lane]);
                #pragma unroll
                for (int m = 0; m < 2; m++) {
                    unsigned A4[4];
                    ldsm_x4(A4, sF_u32 + (((m * 16) * SAW + ks * 8) << 2) + laneoff);
                    mma_f32(C[m], A4, bb2.x, bb2.y);
                }
            }
            const float b20 = __ldg(bf2 + c0), b21 = __ldg(bf2 + c0 + 1);
            #pragma unroll
            for (int m = 0; m < 2; m++) {
                const int rA = m * 16 + g;       // row; batch = b0q + (r>>3), tok = r&7
                const int rB = rA + 8;
                float* oA = out + ((size_t)(b0q + (rA >> 3)) * NTOK + (rA & 7)) * CDIM;
                float* oB = out + ((size_t)(b0q + (rB >> 3)) * NTOK + (rB & 7)) * CDIM;
                *(float2*)&oA[c0] = make_float2(C[m][0] + b20 + xC[m][0], C[m][1] + b21 + xC[m][1]);
                *(float2*)&oB[c0] = make_float2(C[m][2] + b20 + xC[m][2], C[m][3] + b21 + xC[m][3]);
            }
        }
    }
}

// ---------------- launch ----------------
extern "C" void kernel_launch(void* const* d_in, const int* in_sizes, int n_in,
                              void* d_out, int out_size)
{
    const float* query = (const float*)d_in[0];
    const float* tgt   = (const float*)d_in[1];
    const float* ln1_g = (const float*)d_in[2];
    const float* ln1_b = (const float*)d_in[3];
    const float* ln2_g = (const float*)d_in[4];
    const float* ln2_b = (const float*)d_in[5];
    const float* Wq    = (const float*)d_in[6];
    const float* bq    = (const float*)d_in[7];
    const float* Wk    = (const float*)d_in[8];
    const float* Wv    = (const float*)d_in[10];
    const float* bv    = (const float*)d_in[11];
    const float* Wp    = (const float*)d_in[12];
    const float* bp    = (const float*)d_in[13];
    const float* Wf1   = (const float*)d_in[14];
    const float* bf1   = (const float*)d_in[15];
    const float* Wf2   = (const float*)d_in[16];
    const float* bf2   = (const float*)d_in[17];
    float* out = (float*)d_out;

    const int B = in_sizes[1] / (LTOK * CDIM);
    const int nquads = B / 4;
    int grid = 296;
    if (grid > nquads) grid = nquads;

    cudaFuncSetAttribute(mega_kernel, cudaFuncAttributeMaxDynamicSharedMemorySize, SM_MEGA_BYTES);

    precompute_kernel<<<72, 256>>>(query, ln1_g, ln1_b, Wq, bq, Wk, Wv, Wp, Wf1, Wf2);
    mega_kernel<<<grid, 512, SM_MEGA_BYTES>>>(
        tgt, query, bv, bp, ln2_g, ln2_b, bf1, bf2, out, nquads);
}

// round 13
// speedup vs baseline: 1.2586x; 1.0654x over previous
#include <cuda_runtime.h>
#include <cuda_fp16.h>
#include <math.h>

#define CDIM   128
#define LTOK   54
#define NTOK   8
#define LN_EPS 1e-5f
#define SAW    68      // smem row stride in f16x2 words (17x16B -> ldmatrix conflict-free)
#define SDW    33      // dots row stride in f16x2 words
#define SXW    66      // x (f16) row stride in f16x2 words (EVEN: uint2-aligned rows)

// ---------------- device globals (precomputed weights, f16 fragment order) ----------------
__device__ uint2 g_WcB [8 * 24 * 32];   // combined [A_fold | Wv] f16 B-frags
__device__ uint2 g_WpB [8 * 16 * 32];   // Wp  f16 B-frags
__device__ uint2 g_Wf1B[8 * 16 * 32];   // Wf1 f16 B-frags
__device__ uint2 g_Wf2B[8 * 16 * 32];   // Wf2 f16 B-frags

// ---------------- helpers ----------------
__device__ __forceinline__ unsigned hpack(float lo, float hi) {
    __half2 h = __floats2half2_rn(lo, hi);
    return *(unsigned*)&h;
}
__device__ __forceinline__ float2 hunpack(unsigned u) {
    return __half22float2(*(__half2*)&u);
}

__device__ __forceinline__ void mma_f32(float* c, const unsigned* a, unsigned b0, unsigned b1) {
    asm volatile(
        "mma.sync.aligned.m16n8k16.row.col.f32.f16.f16.f32 "
        "{%0,%1,%2,%3},{%4,%5,%6,%7},{%8,%9},{%0,%1,%2,%3};"
        : "+f"(c[0]), "+f"(c[1]), "+f"(c[2]), "+f"(c[3])
        : "r"(a[0]), "r"(a[1]), "r"(a[2]), "r"(a[3]), "r"(b0), "r"(b1));
}

__device__ __forceinline__ void mma_f16(unsigned* c, const unsigned* a, unsigned b0, unsigned b1) {
    asm volatile(
        "mma.sync.aligned.m16n8k16.row.col.f16.f16.f16.f16 "
        "{%0,%1},{%2,%3,%4,%5},{%6,%7},{%0,%1};"
        : "+r"(c[0]), "+r"(c[1])
        : "r"(a[0]), "r"(a[1]), "r"(a[2]), "r"(a[3]), "r"(b0), "r"(b1));
}

__device__ __forceinline__ void ldsm_x4(unsigned* r, unsigned saddr) {
    asm volatile(
        "ldmatrix.sync.aligned.m8n8.x4.shared.b16 {%0,%1,%2,%3}, [%4];"
        : "=r"(r[0]), "=r"(r[1]), "=r"(r[2]), "=r"(r[3]) : "r"(saddr));
}

__device__ __forceinline__ float warp_sum(float v) {
    v += __shfl_xor_sync(0xffffffffu, v, 16);
    v += __shfl_xor_sync(0xffffffffu, v, 8);
    v += __shfl_xor_sync(0xffffffffu, v, 4);
    v += __shfl_xor_sync(0xffffffffu, v, 2);
    v += __shfl_xor_sync(0xffffffffu, v, 1);
    return v;
}

// ---------------- precompute: 72 blocks x 256 threads = 18432 pack items ----------------
__global__ __launch_bounds__(256, 4) void precompute_kernel(
    const float* __restrict__ query,
    const float* __restrict__ ln1_g, const float* __restrict__ ln1_b,
    const float* __restrict__ Wq, const float* __restrict__ bq,
    const float* __restrict__ Wk,
    const float* __restrict__ Wv,
    const float* __restrict__ Wp,
    const float* __restrict__ Wf1,
    const float* __restrict__ Wf2)
{
    __shared__ float s_qn[NTOK * CDIM];
    __shared__ float s_q[NTOK * CDIM];
    const int tid = threadIdx.x;
    const int warp = tid >> 5, lane = tid & 31;

    if (warp < NTOK) {
        const int r = warp;
        float4 xv = *(const float4*)&query[r * CDIM + lane * 4];
        float s1 = xv.x + xv.y + xv.z + xv.w;
        float s2 = xv.x * xv.x + xv.y * xv.y + xv.z * xv.z + xv.w * xv.w;
        s1 = warp_sum(s1);
        s2 = warp_sum(s2);
        float m = s1 * (1.0f / 128.0f);
        float var = s2 * (1.0f / 128.0f) - m * m;
        float rs = rsqrtf(var + LN_EPS);
        float4 g = *(const float4*)&ln1_g[lane * 4];
        float4 be = *(const float4*)&ln1_b[lane * 4];
        float4 o;
        o.x = (xv.x - m) * rs * g.x + be.x;
        o.y = (xv.y - m) * rs * g.y + be.y;
        o.z = (xv.z - m) * rs * g.z + be.z;
        o.w = (xv.w - m) * rs * g.w + be.w;
        *(float4*)&s_qn[r * CDIM + lane * 4] = o;
    }
    __syncthreads();

    #pragma unroll
    for (int j = 0; j < 4; j++) {
        const int idx = tid + j * 256;
        const int t = idx >> 7, o = idx & 127;
        float acc = bq[o];
        #pragma unroll 8
        for (int c = 0; c < CDIM; c++)
            acc += s_qn[t * CDIM + c] * __ldg(Wq + c * CDIM + o);
        s_q[idx] = acc;
    }
    __syncthreads();

    const int gid = blockIdx.x * 256 + tid;
    if (gid < 6144) {
        const int lane2 = gid & 31;
        const int rest = gid >> 5;
        const int nt = rest % 24;
        const int ks = rest / 24;
        const int g = lane2 >> 2, t = lane2 & 3;
        const int c = nt * 8 + g;
        const int k0 = ks * 16 + 2 * t;
        float f0, f1, f2, f3;
        if (c < 64) {
            // A_fold: bk folds to per-column constant -> cancels in softmax
            const int tok = c >> 3, h = c & 7;
            const float* qv = s_q + tok * CDIM + h * 16;
            float a0 = 0.f, a1 = 0.f, a2 = 0.f, a3 = 0.f;
            #pragma unroll
            for (int j = 0; j < 16; j++) {
                const float qj = qv[j];
                a0 += qj * __ldg(Wk + (k0    ) * CDIM + h * 16 + j);
                a1 += qj * __ldg(Wk + (k0 + 1) * CDIM + h * 16 + j);
                a2 += qj * __ldg(Wk + (k0 + 8) * CDIM + h * 16 + j);
                a3 += qj * __ldg(Wk + (k0 + 9) * CDIM + h * 16 + j);
            }
            f0 = 0.25f * a0; f1 = 0.25f * a1; f2 = 0.25f * a2; f3 = 0.25f * a3;
        } else {
            const int cc = c - 64;
            f0 = __ldg(Wv + (k0    ) * CDIM + cc);
            f1 = __ldg(Wv + (k0 + 1) * CDIM + cc);
            f2 = __ldg(Wv + (k0 + 8) * CDIM + cc);
            f3 = __ldg(Wv + (k0 + 9) * CDIM + cc);
        }
        g_WcB[gid] = make_uint2(hpack(f0, f1), hpack(f2, f3));
    } else {
        const int r = (gid - 6144) & 4095;
        const int m = (gid - 6144) >> 12;
        const int lane2 = r & 31;
        const int rest = r >> 5;
        const int nt = rest & 15;
        const int ks = rest >> 4;
        const int g = lane2 >> 2, t = lane2 & 3;
        const int c = nt * 8 + g;
        const int k0 = ks * 16 + 2 * t;
        const float* W = (m == 0) ? Wp : (m == 1) ? Wf1 : Wf2;
        uint2 v = make_uint2(
            hpack(__ldg(W + k0 * CDIM + c), __ldg(W + (k0 + 1) * CDIM + c)),
            hpack(__ldg(W + (k0 + 8) * CDIM + c), __ldg(W + (k0 + 9) * CDIM + c)));
        if (m == 0)      g_WpB [r] = v;
        else if (m == 1) g_Wf1B[r] = v;
        else             g_Wf2B[r] = v;
    }
}

// ---------------- persistent megakernel: 512 threads, 2 blocks/SM ----------------
// Processes a QUAD (4 batches = 2 pairs) per loop iteration.
// Tail GEMMs run on warps 0-7 (2 n-tiles each); warps 8-15 prestage the next
// quad's first tgt pair into sA during the proj phase (sA is dead there).
#define W_A   (112 * SAW)
#define W_B   (6144 * 2)
#define W_D   (108 * SDW)
#define W_AT  (32 * SAW)
#define W_XH  (32 * SXW)
#define OFF_B  (W_A)
#define OFF_D  (W_A + W_B)
#define OFF_AT (W_A + W_B + W_D)
#define OFF_XH (W_A + W_B + W_D + W_AT)
#define SM_MEGA_BYTES ((W_A + W_B + W_D + W_AT + W_XH) * 4)

__global__ __launch_bounds__(512, 2) void mega_kernel(
    const float* __restrict__ tgt,
    const float* __restrict__ query,
    const float* __restrict__ bv,
    const float* __restrict__ bp,
    const float* __restrict__ ln2_g, const float* __restrict__ ln2_b,
    const float* __restrict__ bf1, const float* __restrict__ bf2,
    float* __restrict__ out, int nquads)
{
    extern __shared__ unsigned smw[];
    unsigned* sA  = smw;
    uint2*    sB  = (uint2*)(smw + OFF_B);
    unsigned* sDb = smw + OFF_D;
    unsigned* sF  = smw + OFF_D;          // overlays dots (dead when sF live)
    unsigned* sAt = smw + OFF_AT;
    unsigned* sXh = smw + OFF_XH;

    const int tid = threadIdx.x;
    const int w = tid >> 5, lane = tid & 31;
    const int g = lane >> 2, t = lane & 3;

    const unsigned sA_u32  = (unsigned)__cvta_generic_to_shared(sA);
    const unsigned sAt_u32 = (unsigned)__cvta_generic_to_shared(sAt);
    const unsigned sF_u32  = (unsigned)__cvta_generic_to_shared(sF);
    const unsigned laneoff = (((lane & 15) * SAW + (lane >> 4) * 4) << 2);

    // ---- stage GEMM1 B-fragments ONCE per block ----
    {
        const uint4* src = (const uint4*)g_WcB;
        uint4* dst = (uint4*)sB;
        #pragma unroll
        for (int i = 0; i < 6; i++)
            dst[tid + i * 512] = __ldg(src + tid + i * 512);
    }

    bool pre = false;   // pair-0 tgt of current quad already staged into sA?

    for (int quad = blockIdx.x; quad < nquads; quad += gridDim.x) {
        const int b0q = quad * 4;

        // ======== per-pair attention: j = 0, 1 ========
        #pragma unroll 1
        for (int j = 0; j < 2; j++) {
            __syncthreads();   // guard sA / dots reuse

            if (j == 1 || !pre) {
                // ---- stage tgt (2 batches, 108 packed rows) as f16 ----
                const float4* gt = (const float4*)(tgt + (size_t)(b0q + j * 2) * (LTOK * CDIM));
                #pragma unroll
                for (int i0 = 0; i0 < 7; i0++) {
                    const int i = tid + i0 * 512;
                    if (i < 2 * LTOK * 32) {
                        const int row = i >> 5, c4 = i & 31;
                        float4 v = __ldg(gt + i);
                        *(uint2*)&sA[row * SAW + c4 * 2] =
                            make_uint2(hpack(v.x, v.y), hpack(v.z, v.w));
                    }
                }
            }
            __syncthreads();

            // ---- GEMM1 (f16 accum): 2m x 6n per warp; [112(108),128]@[128,192] ----
            {
                const int a = w & 3;          // m-tile pair {2a, 2a+1}
                const int e = w >> 2;         // n-group: tiles e*6 .. e*6+5
                unsigned C[2][6][2];
                #pragma unroll
                for (int m = 0; m < 2; m++)
                    #pragma unroll
                    for (int n = 0; n < 6; n++) {
                        C[m][n][0] = 0u; C[m][n][1] = 0u;
                    }

                const int bbase = e * 6;
                #pragma unroll 2
                for (int ks = 0; ks < 8; ks++) {
                    unsigned A0[4], A1[4];
                    ldsm_x4(A0, sA_u32 + (((a * 2    ) * 16 * SAW + ks * 8) << 2) + laneoff);
                    ldsm_x4(A1, sA_u32 + (((a * 2 + 1) * 16 * SAW + ks * 8) << 2) + laneoff);
                    const uint2* brow = &sB[(ks * 24 + bbase) * 32 + lane];
                    #pragma unroll
                    for (int n = 0; n < 6; n++) {
                        const uint2 B = brow[n * 32];
                        mma_f16(C[0][n], A0, B.x, B.y);
                        mma_f16(C[1][n], A1, B.x, B.y);
                    }
                }
                __syncthreads();   // ALL A reads done before V overwrites sA

                #pragma unroll
                for (int m = 0; m < 2; m++) {
                    const int rA = (a * 2 + m) * 16 + g;   // packed row (>=108 invalid)
                    const int rB = rA + 8;
                    #pragma unroll
                    for (int n = 0; n < 6; n++) {
                        const int nt = bbase + n;
                        if (nt < 8) {
                            const int wrd = nt * 4 + t;
                            if (rA < 108) sDb[rA * SDW + wrd] = C[m][n][0];
                            if (rB < 108) sDb[rB * SDW + wrd] = C[m][n][1];
                        } else {
                            const int wrd = (nt - 8) * 4 + t;
                            if (rA < 108) sA[rA * SAW + wrd] = C[m][n][0];
                            if (rB < 108) sA[rB * SAW + wrd] = C[m][n][1];
                        }
                    }
                }
            }
            __syncthreads();

            // ---- softmax + AV: 512 tasks (2b x 8tok x 8head x 4quarter) ----
            {
                const int bb = tid >> 8;
                const int rest = tid & 255;
                const int th = rest >> 2, qt = rest & 3;
                const int tok = th >> 3, h = th & 7;
                const int ridx = (tok < 2) ? tok : (tok - 2);
                const int hb = ridx / 3, wb = ridx % 3;
                const int l0 = hb * 27 + wb * 3;
                int ls[9];
                #pragma unroll
                for (int d = 0; d < 9; d++) ls[d] = bb * LTOK + l0 + (d / 3) * 9 + (d % 3);

                const int dw = th >> 1, dh = th & 1;
                float dv[9];
                float mx = -1e30f;
                #pragma unroll
                for (int d = 0; d < 9; d++) {
                    float2 p = hunpack(sDb[ls[d] * SDW + dw]);
                    dv[d] = dh ? p.y : p.x;
                    mx = fmaxf(mx, dv[d]);
                }
                float ssum = 0.0f;
                #pragma unroll
                for (int d = 0; d < 9; d++) {
                    dv[d] = __expf(dv[d] - mx);
                    ssum += dv[d];
                }
                const float inv = 1.0f / ssum;
                float acc[4] = {0.f, 0.f, 0.f, 0.f};
                #pragma unroll
                for (int d = 0; d < 9; d++) {
                    const uint2 vv = *(const uint2*)&sA[ls[d] * SAW + h * 8 + qt * 2];
                    float2 p;
                    p = hunpack(vv.x); acc[0] += dv[d] * p.x; acc[1] += dv[d] * p.y;
                    p = hunpack(vv.y); acc[2] += dv[d] * p.x; acc[3] += dv[d] * p.y;
                }
                const int cb = h * 16 + qt * 4;
                const float b0v = __ldg(bv + cb),     b1v = __ldg(bv + cb + 1);
                const float b2v = __ldg(bv + cb + 2), b3v = __ldg(bv + cb + 3);
                *(uint2*)&sAt[(j * 16 + bb * 8 + tok) * SAW + h * 8 + qt * 2] = make_uint2(
                    hpack(acc[0] * inv + b0v, acc[1] * inv + b1v),
                    hpack(acc[2] * inv + b2v, acc[3] * inv + b3v));
            }
        }
        __syncthreads();

        // ===== tail: M=32 x 128 GEMMs; warps 0-7 own 2 n-tiles each =====
        const int nt0 = w * 2;                 // first n-tile (w<8)
        float xC[2][2][4];                     // residual x kept fp32 in regs

        // ---- proj (warps 0-7) ; prestage next quad pair-0 (warps 8-15) ----
        {
            if (w < 8) {
                #pragma unroll
                for (int m = 0; m < 2; m++)
                    #pragma unroll
                    for (int n = 0; n < 2; n++)
                        #pragma unroll
                        for (int q = 0; q < 4; q++) xC[m][n][q] = 0.0f;
                #pragma unroll
                for (int ks = 0; ks < 8; ks++) {
                    unsigned A0[4], A1[4];
                    ldsm_x4(A0, sAt_u32 + ((ks * 8) << 2) + laneoff);
                    ldsm_x4(A1, sAt_u32 + ((16 * SAW + ks * 8) << 2) + laneoff);
                    #pragma unroll
                    for (int n = 0; n < 2; n++) {
                        uint2 bb2 = __ldg(&g_WpB[(ks * 16 + nt0 + n) * 32 + lane]);
                        mma_f32(xC[0][n], A0, bb2.x, bb2.y);
                        mma_f32(xC[1][n], A1, bb2.x, bb2.y);
                    }
                }
                #pragma unroll
                for (int n = 0; n < 2; n++) {
                    const int cn = (nt0 + n) * 8 + 2 * t;
                    const float bp0 = __ldg(bp + cn), bp1 = __ldg(bp + cn + 1);
                    const float q0 = __ldg(query + g * CDIM + cn);
                    const float q1 = __ldg(query + g * CDIM + cn + 1);
                    #pragma unroll
                    for (int m = 0; m < 2; m++) {
                        xC[m][n][0] += bp0 + q0; xC[m][n][1] += bp1 + q1;
                        xC[m][n][2] += bp0 + q0; xC[m][n][3] += bp1 + q1;
                        sXh[(m * 16 + g    ) * SXW + (nt0 + n) * 4 + t] = hpack(xC[m][n][0], xC[m][n][1]);
                        sXh[(m * 16 + g + 8) * SXW + (nt0 + n) * 4 + t] = hpack(xC[m][n][2], xC[m][n][3]);
                    }
                }
            } else {
                const int nextq = quad + gridDim.x;
                if (nextq < nquads) {
                    const float4* gt = (const float4*)(tgt + (size_t)(nextq * 4) * (LTOK * CDIM));
                    const int tid2 = (w - 8) * 32 + lane;   // 0..255
                    #pragma unroll
                    for (int i0 = 0; i0 < 14; i0++) {
                        const int i = tid2 + i0 * 256;
                        if (i < 2 * LTOK * 32) {
                            const int row = i >> 5, c4 = i & 31;
                            float4 v = __ldg(gt + i);
                            *(uint2*)&sA[row * SAW + c4 * 2] =
                                make_uint2(hpack(v.x, v.y), hpack(v.z, v.w));
                        }
                    }
                }
            }
        }
        pre = true;   // next iteration's pair-0 (if any) is staged
        __syncthreads();

        // ---- LN2 (32 rows, all 16 warps, 2 rows each) -> sAt (f16, overwrite) ----
        {
            const float4 gv  = __ldg((const float4*)ln2_g + lane);
            const float4 bv2 = __ldg((const float4*)ln2_b + lane);
            #pragma unroll
            for (int rr = w; rr < 32; rr += 16) {
                uint2 xu = *(const uint2*)&sXh[rr * SXW + lane * 2];
                float2 xa = hunpack(xu.x), xb = hunpack(xu.y);
                float s1 = xa.x + xa.y + xb.x + xb.y;
                float s2 = xa.x * xa.x + xa.y * xa.y + xb.x * xb.x + xb.y * xb.y;
                s1 = warp_sum(s1);
                s2 = warp_sum(s2);
                float m = s1 * (1.0f / 128.0f);
                float var = s2 * (1.0f / 128.0f) - m * m;
                float rs = rsqrtf(var + LN_EPS);
                *(uint2*)&sAt[rr * SAW + lane * 2] = make_uint2(
                    hpack((xa.x - m) * rs * gv.x + bv2.x, (xa.y - m) * rs * gv.y + bv2.y),
                    hpack((xb.x - m) * rs * gv.z + bv2.z, (xb.y - m) * rs * gv.w + bv2.w));
            }
        }
        __syncthreads();

        // ---- f = gelu(ln @ Wf1 + bf1) -> sF (warps 0-7) ----
        if (w < 8) {
            float C[2][2][4];
            #pragma unroll
            for (int m = 0; m < 2; m++)
                #pragma unroll
                for (int n = 0; n < 2; n++)
                    #pragma unroll
                    for (int q = 0; q < 4; q++) C[m][n][q] = 0.0f;
            #pragma unroll
            for (int ks = 0; ks < 8; ks++) {
                unsigned A0[4], A1[4];
                ldsm_x4(A0, sAt_u32 + ((ks * 8) << 2) + laneoff);
                ldsm_x4(A1, sAt_u32 + ((16 * SAW + ks * 8) << 2) + laneoff);
                #pragma unroll
                for (int n = 0; n < 2; n++) {
                    uint2 bb2 = __ldg(&g_Wf1B[(ks * 16 + nt0 + n) * 32 + lane]);
                    mma_f32(C[0][n], A0, bb2.x, bb2.y);
                    mma_f32(C[1][n], A1, bb2.x, bb2.y);
                }
            }
            #pragma unroll
            for (int n = 0; n < 2; n++) {
                const int cn = (nt0 + n) * 8 + 2 * t;
                const float b10 = __ldg(bf1 + cn), b11 = __ldg(bf1 + cn + 1);
                #pragma unroll
                for (int m = 0; m < 2; m++) {
                    float v0 = C[m][n][0] + b10, v1 = C[m][n][1] + b11;
                    float v2 = C[m][n][2] + b10, v3 = C[m][n][3] + b11;
                    v0 = 0.5f * v0 * (1.0f + erff(v0 * 0.70710678118654752f));
                    v1 = 0.5f * v1 * (1.0f + erff(v1 * 0.70710678118654752f));
                    v2 = 0.5f * v2 * (1.0f + erff(v2 * 0.70710678118654752f));
                    v3 = 0.5f * v3 * (1.0f + erff(v3 * 0.70710678118654752f));
                    sF[(m * 16 + g    ) * SAW + (nt0 + n) * 4 + t] = hpack(v0, v1);
                    sF[(m * 16 + g + 8) * SAW + (nt0 + n) * 4 + t] = hpack(v2, v3);
                }
            }
        }
        __syncthreads();

        // ---- out = x + f @ Wf2 + bf2  (warps 0-7; x from regs, fp32) ----
        if (w < 8) {
            float C[2][2][4];
            #pragma unroll
            for (int m = 0; m < 2; m++)
                #pragma unroll
                for (int n = 0; n < 2; n++)
                    #pragma unroll
                    for (int q = 0; q < 4; q++) C[m][n][q] = 0.0f;
            #pragma unroll
            for (int ks = 0; ks < 8; ks++) {
                unsigned A0[4], A1[4];
                ldsm_x4(A0, sF_u32 + ((ks * 8) << 2) + laneoff);
                ldsm_x4(A1, sF_u32 + ((16 * SAW + ks * 8) << 2) + laneoff);
                #pragma unroll
                for (int n = 0; n < 2; n++) {
                    uint2 bb2 = __ldg(&g_Wf2B[(ks * 16 + nt0 + n) * 32 + lane]);
                    mma_f32(C[0][n], A0, bb2.x, bb2.y);
                    mma_f32(C[1][n], A1, bb2.x, bb2.y);
                }
            }
            #pragma unroll
            for (int n = 0; n < 2; n++) {
                const int cn = (nt0 + n) * 8 + 2 * t;
                const float b20 = __ldg(bf2 + cn), b21 = __ldg(bf2 + cn + 1);
                #pragma unroll
                for (int m = 0; m < 2; m++) {
                    const int rA = m * 16 + g;       // row; batch = b0q + (r>>3), tok = r&7
                    const int rB = rA + 8;
                    float* oA = out + ((size_t)(b0q + (rA >> 3)) * NTOK + (rA & 7)) * CDIM;
                    float* oB = out + ((size_t)(b0q + (rB >> 3)) * NTOK + (rB & 7)) * CDIM;
                    *(float2*)&oA[cn] = make_float2(C[m][n][0] + b20 + xC[m][n][0],
                                                    C[m][n][1] + b21 + xC[m][n][1]);
                    *(float2*)&oB[cn] = make_float2(C[m][n][2] + b20 + xC[m][n][2],
                                                    C[m][n][3] + b21 + xC[m][n][3]);
                }
            }
        }
    }
}

// ---------------- launch ----------------
extern "C" void kernel_launch(void* const* d_in, const int* in_sizes, int n_in,
                              void* d_out, int out_size)
{
    const float* query = (const float*)d_in[0];
    const float* tgt   = (const float*)d_in[1];
    const float* ln1_g = (const float*)d_in[2];
    const float* ln1_b = (const float*)d_in[3];
    const float* ln2_g = (const float*)d_in[4];
    const float* ln2_b = (const float*)d_in[5];
    const float* Wq    = (const float*)d_in[6];
    const float* bq    = (const float*)d_in[7];
    const float* Wk    = (const float*)d_in[8];
    const float* Wv    = (const float*)d_in[10];
    const float* bv    = (const float*)d_in[11];
    const float* Wp    = (const float*)d_in[12];
    const float* bp    = (const float*)d_in[13];
    const float* Wf1   = (const float*)d_in[14];
    const float* bf1   = (const float*)d_in[15];
    const float* Wf2   = (const float*)d_in[16];
    const float* bf2   = (const float*)d_in[17];
    float* out = (float*)d_out;

    const int B = in_sizes[1] / (LTOK * CDIM);
    const int nquads = B / 4;
    int grid = 296;
    if (grid > nquads) grid = nquads;

    cudaFuncSetAttribute(mega_kernel, cudaFuncAttributeMaxDynamicSharedMemorySize, SM_MEGA_BYTES);

    precompute_kernel<<<72, 256>>>(query, ln1_g, ln1_b, Wq, bq, Wk, Wv, Wp, Wf1, Wf2);
    mega_kernel<<<grid, 512, SM_MEGA_BYTES>>>(
        tgt, query, bv, bp, ln2_g, ln2_b, bf1, bf2, out, nquads);
}